// round 13
// baseline (speedup 1.0000x reference)
#include <cuda_runtime.h>

#define NB 4
#define NC 64
#define NS 4
#define NM 6
#define HS 64
#define WS 64
#define HH 256
#define WW 256
#define NG 12
#define NROWS (NS * NS * NM * NM * NC)   // 36864 rows of 64 floats
#define PREP_BLKS 288                    // half-row (32 floats) per thread
#define GRID (NB * NC * NS * NS)         // 4096

// Per-row means of w over C_OUT (incl. 1/64/4096): g_wsum[uv][i][j][c]
__device__ float g_wsum[NROWS];
// Final per-(u,v,c) monomial coefficients g[0..11]
__device__ float g_gcoef[NS * NS * NC * NG];
// Producer/consumer state (all zero-initialized; reset each launch by last block)
__device__ unsigned int g_cnt;     // prep block arrivals
__device__ unsigned int g_ready;   // transform published
__device__ unsigned int g_done;    // blocks finished (for reset)

// Monomial coefficients of Chebyshev T_r (row r, column m)
__constant__ float c_cheb[NG][NG] = {
  {1,0,0,0,0,0,0,0,0,0,0,0},
  {0,1,0,0,0,0,0,0,0,0,0,0},
  {-1,0,2,0,0,0,0,0,0,0,0,0},
  {0,-3,0,4,0,0,0,0,0,0,0,0},
  {1,0,-8,0,8,0,0,0,0,0,0,0},
  {0,5,0,-20,0,16,0,0,0,0,0,0},
  {-1,0,18,0,-48,0,32,0,0,0,0,0},
  {0,-7,0,56,0,-112,0,64,0,0,0,0},
  {1,0,-32,0,160,0,-256,0,128,0,0,0},
  {0,9,0,-120,0,432,0,-576,0,256,0,0},
  {-1,0,50,0,-400,0,1120,0,-1280,0,512,0},
  {0,-11,0,220,0,-1232,0,2816,0,-2816,0,1024}
};

#define ABSI(x) ((x) < 0 ? -(x) : (x))
#define ACCUM(i, j) { float wv = g_wsum[((uv * 36 + (i) * 6 + (j)) << 6) + c];   \
    if ((i) != (j)) wv += g_wsum[((uv * 36 + (j) * 6 + (i)) << 6) + c];          \
    wv *= 0.25f;                                                                  \
    h[(i)+(j)+1] += wv; h[ABSI((i)+(j)-1)] += wv;                                 \
    h[(j)-(i)+1] += wv; h[ABSI((j)-(i)-1)] += wv; }

// ---- packed fp32x2 helpers (sm_100+) ----
typedef unsigned long long u64t;

__device__ __forceinline__ u64t pk2(float lo, float hi) {
    u64t r; asm("mov.b64 %0, {%1,%2};" : "=l"(r) : "f"(lo), "f"(hi)); return r;
}
__device__ __forceinline__ void upk2(u64t v, float& lo, float& hi) {
    asm("mov.b64 {%0,%1}, %2;" : "=f"(lo), "=f"(hi) : "l"(v));
}
__device__ __forceinline__ u64t fma2(u64t a, u64t b, u64t c) {
    u64t d; asm("fma.rn.f32x2 %0, %1, %2, %3;" : "=l"(d) : "l"(a), "l"(b), "l"(c)); return d;
}
__device__ __forceinline__ u64t add2(u64t a, u64t b) {
    u64t d; asm("add.rn.f32x2 %0, %1, %2;" : "=l"(d) : "l"(a), "l"(b)); return d;
}

// Single fused kernel. Blocks 0..287 produce the folded weight coefficients
// (rowsum -> arrival counter -> last block transforms & publishes). ALL blocks
// load their x segment + min/max first (hides the producer phase), spin on
// g_ready, then run the degree-11 Horner accumulation and broadcast-store.
// launch_bounds(256,4) caps regs at 64 => 4 CTAs/SM => 592-CTA first wave,
// so all 288 producer blocks are resident: spin-wait cannot deadlock.
__global__ __launch_bounds__(256, 4) void cft_fused_kernel(const float* __restrict__ x,
                                                           const float* __restrict__ w,
                                                           float* __restrict__ out) {
    int bid = blockIdx.x;
    int tid = threadIdx.x;
    int lane = tid & 31, warp = tid >> 5;

    // ================= producer part (blocks 0..PREP_BLKS-1) =================
    if (bid < PREP_BLKS) {
        int t = bid * 256 + tid;          // 0..73727
        int r = t >> 1;                   // row 0..36863
        int q = t & 1;                    // half within row
        const float4* __restrict__ p = (const float4*)w + (size_t)r * 16 + q * 8;
        float4 v0 = __ldcs(p + 0), v1 = __ldcs(p + 1), v2 = __ldcs(p + 2), v3 = __ldcs(p + 3);
        float4 v4 = __ldcs(p + 4), v5 = __ldcs(p + 5), v6 = __ldcs(p + 6), v7 = __ldcs(p + 7);
        float s = ((v0.x + v0.y) + (v0.z + v0.w)) + ((v1.x + v1.y) + (v1.z + v1.w))
                + ((v2.x + v2.y) + (v2.z + v2.w)) + ((v3.x + v3.y) + (v3.z + v3.w))
                + ((v4.x + v4.y) + (v4.z + v4.w)) + ((v5.x + v5.y) + (v5.z + v5.w))
                + ((v6.x + v6.y) + (v6.z + v6.w)) + ((v7.x + v7.y) + (v7.z + v7.w));
        s += __shfl_xor_sync(0xffffffffu, s, 1);
        if (q == 0)
            g_wsum[r] = s * (1.0f / (64.0f * 4096.0f));

        __shared__ bool s_last;
        __syncthreads();
        if (tid == 0) {
            __threadfence();             // release our g_wsum writes
            s_last = (atomicAdd(&g_cnt, 1u) == PREP_BLKS - 1u);
        }
        __syncthreads();
        if (s_last) {
            __threadfence();             // acquire all g_wsum writes
            for (int slot = tid; slot < NS * NS * NC; slot += 256) {
                int uv = slot >> 6;
                int c = slot & 63;
                float h[NG];
                #pragma unroll
                for (int r2 = 0; r2 < NG; r2++) h[r2] = 0.f;
                ACCUM(0,0) ACCUM(0,1) ACCUM(0,2) ACCUM(0,3) ACCUM(0,4) ACCUM(0,5)
                ACCUM(1,1) ACCUM(1,2) ACCUM(1,3) ACCUM(1,4) ACCUM(1,5)
                ACCUM(2,2) ACCUM(2,3) ACCUM(2,4) ACCUM(2,5)
                ACCUM(3,3) ACCUM(3,4) ACCUM(3,5)
                ACCUM(4,4) ACCUM(4,5)
                ACCUM(5,5)
                #pragma unroll
                for (int m = 0; m < NG; m++) {
                    float g = 0.f;
                    #pragma unroll
                    for (int r2 = 0; r2 < NG; r2++) g = fmaf(h[r2], c_cheb[r2][m], g);
                    g_gcoef[(size_t)slot * NG + m] = g;
                }
            }
            __syncthreads();
            if (tid == 0) {
                __threadfence();         // release g_gcoef
                atomicExch(&g_ready, 1u);
            }
        }
    }

    // ================= consumer part (all blocks) =================
    int seg = bid;                     // ((b*64+c)*4+u)*4+v
    int v = seg & 3;
    int u = (seg >> 2) & 3;
    int bc = seg >> 4;
    int c = bc & 63;
    size_t base = (size_t)bc * (HH * WW) + (size_t)u * HS * WW + (size_t)v * WS;
    const float4* __restrict__ xin = (const float4*)(x + base);

    float4 d[4];
    #pragma unroll
    for (int it = 0; it < 4; it++) {
        int q = it * 256 + tid;
        d[it] = __ldcs(xin + (q >> 4) * (WW / 4) + (q & 15));
    }

    // ---- pass 1: per-segment min/max (overlaps producer phase) ----
    float mn = d[0].x, mx = d[0].x;
    #pragma unroll
    for (int it = 0; it < 4; it++) {
        mn = fminf(mn, fminf(fminf(d[it].x, d[it].y), fminf(d[it].z, d[it].w)));
        mx = fmaxf(mx, fmaxf(fmaxf(d[it].x, d[it].y), fmaxf(d[it].z, d[it].w)));
    }
    #pragma unroll
    for (int off = 16; off; off >>= 1) {
        mn = fminf(mn, __shfl_xor_sync(0xffffffffu, mn, off));
        mx = fmaxf(mx, __shfl_xor_sync(0xffffffffu, mx, off));
    }
    __shared__ float s_mn[8], s_mx[8];
    __shared__ float s_part[8];
    if (lane == 0) { s_mn[warp] = mn; s_mx[warp] = mx; }
    __syncthreads();
    mn = s_mn[0]; mx = s_mx[0];
    #pragma unroll
    for (int k = 1; k < 8; k++) { mn = fminf(mn, s_mn[k]); mx = fmaxf(mx, s_mx[k]); }

    // ---- wait for coefficients ----
    if (tid == 0) {
        while (atomicAdd(&g_ready, 0u) == 0u) __nanosleep(64);
        __threadfence();               // acquire g_gcoef
    }
    __syncthreads();

    const float* __restrict__ gp = g_gcoef + ((size_t)((u * NS + v) * NC) + c) * NG;
    float gs[NG];
    #pragma unroll
    for (int m = 0; m < NG; m++) gs[m] = __ldcg(gp + m);   // L2 read (fresh)

    // ---- pass 2: packed Horner accumulation ----
    float a = 2.0f / (mx - mn + 1e-8f);
    float bb = fmaf(-mn, a, -1.0f);        // xn = x*a + bb
    u64t a2 = pk2(a, a);
    u64t b2 = pk2(bb, bb);
    u64t G[NG];
    #pragma unroll
    for (int m = 0; m < NG; m++) G[m] = pk2(gs[m], gs[m]);

    u64t acc = 0ull;   // {+0.0f,+0.0f}
    #pragma unroll
    for (int it = 0; it < 4; it++) {
        #pragma unroll
        for (int half = 0; half < 2; half++) {
            u64t val2 = half ? pk2(d[it].z, d[it].w) : pk2(d[it].x, d[it].y);
            u64t xn = fma2(val2, a2, b2);
            u64t p = G[11];
            #pragma unroll
            for (int m = 10; m >= 0; m--) p = fma2(p, xn, G[m]);
            acc = add2(acc, p);
        }
    }

    // ---- reduce one scalar across block; all threads finish redundantly ----
    float lo, hi; upk2(acc, lo, hi);
    float part = lo + hi;
    #pragma unroll
    for (int off = 16; off; off >>= 1)
        part += __shfl_xor_sync(0xffffffffu, part, off);
    if (lane == 0) s_part[warp] = part;
    __syncthreads();
    float s = s_part[0];
    #pragma unroll
    for (int k = 1; k < 8; k++) s += s_part[k];
    float sig = tanhf(s);

    // ---- broadcast-store the segment (streaming stores) ----
    float4 o4 = make_float4(sig, sig, sig, sig);
    float4* oo = (float4*)(out + base);
    #pragma unroll
    for (int it = 0; it < 4; it++) {
        int q = it * 256 + tid;
        __stcs(oo + (q >> 4) * (WW / 4) + (q & 15), o4);
    }

    // ---- replay-safe reset: last finishing block zeroes the state ----
    __syncthreads();
    if (tid == 0) {
        __threadfence();
        if (atomicAdd(&g_done, 1u) == GRID - 1u) {
            g_cnt = 0; g_ready = 0; g_done = 0;
        }
    }
}

extern "C" void kernel_launch(void* const* d_in, const int* in_sizes, int n_in,
                              void* d_out, int out_size) {
    const float* x = (const float*)d_in[0];
    const float* w = (const float*)d_in[1];
    float* out = (float*)d_out;
    cft_fused_kernel<<<GRID, 256>>>(x, w, out);
}

// round 15
// speedup vs baseline: 1.2617x; 1.2617x over previous
#include <cuda_runtime.h>

#define NB 4
#define NC 64
#define NS 4
#define NM 6
#define HS 64
#define WS 64
#define HH 256
#define WW 256
#define NG 12
#define NROWS (NS * NS * NM * NM * NC)   // 36864 rows of 64 floats
#define PREP_BLOCKS (NROWS * 4 / 256)    // 576

// Per-row means of w over C_OUT (incl. 1/64/4096): g_wsum[uv][i][j][c]
__device__ float g_wsum[NROWS];
// Final per-(u,v,c) monomial coefficients g[0..11]
__device__ float g_gcoef[NS * NS * NC * NG];
// Arrival counter for in-kernel rowsum->transform handoff (reset after use).
__device__ unsigned int g_cnt;

// Monomial coefficients of Chebyshev T_r (row r, column m)
__constant__ float c_cheb[NG][NG] = {
  {1,0,0,0,0,0,0,0,0,0,0,0},
  {0,1,0,0,0,0,0,0,0,0,0,0},
  {-1,0,2,0,0,0,0,0,0,0,0,0},
  {0,-3,0,4,0,0,0,0,0,0,0,0},
  {1,0,-8,0,8,0,0,0,0,0,0,0},
  {0,5,0,-20,0,16,0,0,0,0,0,0},
  {-1,0,18,0,-48,0,32,0,0,0,0,0},
  {0,-7,0,56,0,-112,0,64,0,0,0,0},
  {1,0,-32,0,160,0,-256,0,128,0,0,0},
  {0,9,0,-120,0,432,0,-576,0,256,0,0},
  {-1,0,50,0,-400,0,1120,0,-1280,0,512,0},
  {0,-11,0,220,0,-1232,0,2816,0,-2816,0,1024}
};

#define ABSI(x) ((x) < 0 ? -(x) : (x))
#define ACCUM(i, j) { float wv = g_wsum[((uv * 36 + (i) * 6 + (j)) << 6) + c];   \
    if ((i) != (j)) wv += g_wsum[((uv * 36 + (j) * 6 + (i)) << 6) + c];          \
    wv *= 0.25f;                                                                  \
    h[(i)+(j)+1] += wv; h[ABSI((i)+(j)-1)] += wv;                                 \
    h[(j)-(i)+1] += wv; h[ABSI((j)-(i)-1)] += wv; }

// grid = 576 x 256. Quarter-row (4 float4) per thread, 4 lanes/row (the
// measured-5.7us config). Last-arriving block runs the 21-pair -> monomial
// transform inline; the kernel boundary publishes g_gcoef to the main kernel.
__global__ void prep_kernel(const float* __restrict__ w) {
    int t = blockIdx.x * 256 + threadIdx.x;   // 0..147455
    int r = t >> 2;                           // row 0..36863
    int q = t & 3;                            // quarter within row
    const float4* __restrict__ p = (const float4*)w + (size_t)r * 16 + q * 4;
    float4 v0 = __ldcs(p + 0);
    float4 v1 = __ldcs(p + 1);
    float4 v2 = __ldcs(p + 2);
    float4 v3 = __ldcs(p + 3);
    float s = ((v0.x + v0.y) + (v0.z + v0.w)) + ((v1.x + v1.y) + (v1.z + v1.w))
            + ((v2.x + v2.y) + (v2.z + v2.w)) + ((v3.x + v3.y) + (v3.z + v3.w));
    s += __shfl_xor_sync(0xffffffffu, s, 2);
    s += __shfl_xor_sync(0xffffffffu, s, 1);
    if (q == 0)
        g_wsum[r] = s * (1.0f / (64.0f * 4096.0f));

    // ---- arrival counter: last block does the transform ----
    __shared__ bool s_last;
    __syncthreads();                 // block's g_wsum writes issued
    if (threadIdx.x == 0) {
        __threadfence();             // release our g_wsum writes
        s_last = (atomicAdd(&g_cnt, 1u) == PREP_BLOCKS - 1u);
    }
    __syncthreads();
    if (!s_last) return;
    __threadfence();                 // acquire all blocks' g_wsum writes

    for (int slot = threadIdx.x; slot < NS * NS * NC; slot += 256) {
        int uv = slot >> 6;
        int c = slot & 63;
        float h[NG];
        #pragma unroll
        for (int r2 = 0; r2 < NG; r2++) h[r2] = 0.f;
        ACCUM(0,0) ACCUM(0,1) ACCUM(0,2) ACCUM(0,3) ACCUM(0,4) ACCUM(0,5)
        ACCUM(1,1) ACCUM(1,2) ACCUM(1,3) ACCUM(1,4) ACCUM(1,5)
        ACCUM(2,2) ACCUM(2,3) ACCUM(2,4) ACCUM(2,5)
        ACCUM(3,3) ACCUM(3,4) ACCUM(3,5)
        ACCUM(4,4) ACCUM(4,5)
        ACCUM(5,5)
        #pragma unroll
        for (int m = 0; m < NG; m++) {
            float g = 0.f;
            #pragma unroll
            for (int r2 = 0; r2 < NG; r2++) g = fmaf(h[r2], c_cheb[r2][m], g);
            g_gcoef[(size_t)slot * NG + m] = g;
        }
    }
    __syncthreads();
    if (threadIdx.x == 0) g_cnt = 0;   // reset for next graph replay
}

// ---- packed fp32x2 helpers (sm_100+) ----
typedef unsigned long long u64t;

__device__ __forceinline__ u64t pk2(float lo, float hi) {
    u64t r; asm("mov.b64 %0, {%1,%2};" : "=l"(r) : "f"(lo), "f"(hi)); return r;
}
__device__ __forceinline__ void upk2(u64t v, float& lo, float& hi) {
    asm("mov.b64 {%0,%1}, %2;" : "=f"(lo), "=f"(hi) : "l"(v));
}
__device__ __forceinline__ u64t fma2(u64t a, u64t b, u64t c) {
    u64t d; asm("fma.rn.f32x2 %0, %1, %2, %3;" : "=l"(d) : "l"(a), "l"(b), "l"(c)); return d;
}
__device__ __forceinline__ u64t add2(u64t a, u64t b) {
    u64t d; asm("add.rn.f32x2 %0, %1, %2;" : "=l"(d) : "l"(a), "l"(b)); return d;
}

// One CTA per (b,c,u,v) segment. 256 threads, 16 px/thread in regs.
// Streaming loads/stores; G coeffs prefetched to overlap min/max pass.
__global__ __launch_bounds__(256, 4) void cft_main_kernel(const float* __restrict__ x,
                                                          float* __restrict__ out) {
    int seg = blockIdx.x;              // ((b*64+c)*4+u)*4+v
    int v = seg & 3;
    int u = (seg >> 2) & 3;
    int bc = seg >> 4;
    int c = bc & 63;
    size_t base = (size_t)bc * (HH * WW) + (size_t)u * HS * WW + (size_t)v * WS;
    const float4* __restrict__ xin = (const float4*)(x + base);
    int tid = threadIdx.x;
    int lane = tid & 31, warp = tid >> 5;

    float4 d[4];
    #pragma unroll
    for (int it = 0; it < 4; it++) {
        int q = it * 256 + tid;
        d[it] = __ldcs(xin + (q >> 4) * (WW / 4) + (q & 15));
    }

    // Issue the 12 coefficient loads NOW so their latency overlaps the min/max.
    const float* __restrict__ gp = g_gcoef + ((size_t)((u * NS + v) * NC) + c) * NG;
    float gs[NG];
    #pragma unroll
    for (int m = 0; m < NG; m++) gs[m] = __ldg(gp + m);

    // ---- pass 1: per-segment min/max ----
    float mn = d[0].x, mx = d[0].x;
    #pragma unroll
    for (int it = 0; it < 4; it++) {
        mn = fminf(mn, fminf(fminf(d[it].x, d[it].y), fminf(d[it].z, d[it].w)));
        mx = fmaxf(mx, fmaxf(fmaxf(d[it].x, d[it].y), fmaxf(d[it].z, d[it].w)));
    }
    #pragma unroll
    for (int off = 16; off; off >>= 1) {
        mn = fminf(mn, __shfl_xor_sync(0xffffffffu, mn, off));
        mx = fmaxf(mx, __shfl_xor_sync(0xffffffffu, mx, off));
    }
    __shared__ float s_mn[8], s_mx[8];
    __shared__ float s_part[8];
    if (lane == 0) { s_mn[warp] = mn; s_mx[warp] = mx; }
    __syncthreads();
    mn = s_mn[0]; mx = s_mx[0];
    #pragma unroll
    for (int k = 1; k < 8; k++) { mn = fminf(mn, s_mn[k]); mx = fmaxf(mx, s_mx[k]); }

    // ---- pass 2: packed Horner accumulation ----
    float a = 2.0f / (mx - mn + 1e-8f);
    float bb = fmaf(-mn, a, -1.0f);        // xn = x*a + bb
    u64t a2 = pk2(a, a);
    u64t b2 = pk2(bb, bb);
    u64t G[NG];
    #pragma unroll
    for (int m = 0; m < NG; m++) G[m] = pk2(gs[m], gs[m]);

    u64t acc = 0ull;   // {+0.0f,+0.0f}
    #pragma unroll
    for (int it = 0; it < 4; it++) {
        #pragma unroll
        for (int half = 0; half < 2; half++) {
            u64t val2 = half ? pk2(d[it].z, d[it].w) : pk2(d[it].x, d[it].y);
            u64t xn = fma2(val2, a2, b2);
            u64t p = G[11];
            #pragma unroll
            for (int m = 10; m >= 0; m--) p = fma2(p, xn, G[m]);
            acc = add2(acc, p);
        }
    }

    // ---- reduce one scalar across block; all threads finish redundantly ----
    float lo, hi; upk2(acc, lo, hi);
    float part = lo + hi;
    #pragma unroll
    for (int off = 16; off; off >>= 1)
        part += __shfl_xor_sync(0xffffffffu, part, off);
    if (lane == 0) s_part[warp] = part;
    __syncthreads();
    float s = s_part[0];
    #pragma unroll
    for (int k = 1; k < 8; k++) s += s_part[k];
    float sig = tanhf(s);

    // ---- broadcast-store the segment (streaming stores) ----
    float4 o4 = make_float4(sig, sig, sig, sig);
    float4* oo = (float4*)(out + base);
    #pragma unroll
    for (int it = 0; it < 4; it++) {
        int q = it * 256 + tid;
        __stcs(oo + (q >> 4) * (WW / 4) + (q & 15), o4);
    }
}

extern "C" void kernel_launch(void* const* d_in, const int* in_sizes, int n_in,
                              void* d_out, int out_size) {
    const float* x = (const float*)d_in[0];
    const float* w = (const float*)d_in[1];
    float* out = (float*)d_out;
    prep_kernel<<<PREP_BLOCKS, 256>>>(w);
    cft_main_kernel<<<NB * NC * NS * NS, 256>>>(x, out);
}

// round 17
// speedup vs baseline: 1.4830x; 1.1754x over previous
#include <cuda_runtime.h>

#define NB 4
#define NC 64
#define NS 4
#define NM 6
#define HS 64
#define WS 64
#define HH 256
#define WW 256
#define NG 12
#define NROWS (NS * NS * NM * NM * NC)   // 36864 rows of 64 floats
#define PREP_BLOCKS (NROWS * 4 / 256)    // 576

// Per-row means of w over C_OUT (incl. 1/64/4096): g_wsum[uv][i][j][c]
__device__ float g_wsum[NROWS];
// Final per-(u,v,c) monomial coefficients g[0..11]
__device__ float g_gcoef[NS * NS * NC * NG];

// Monomial coefficients of Chebyshev T_r (row r, column m)
__constant__ float c_cheb[NG][NG] = {
  {1,0,0,0,0,0,0,0,0,0,0,0},
  {0,1,0,0,0,0,0,0,0,0,0,0},
  {-1,0,2,0,0,0,0,0,0,0,0,0},
  {0,-3,0,4,0,0,0,0,0,0,0,0},
  {1,0,-8,0,8,0,0,0,0,0,0,0},
  {0,5,0,-20,0,16,0,0,0,0,0,0},
  {-1,0,18,0,-48,0,32,0,0,0,0,0},
  {0,-7,0,56,0,-112,0,64,0,0,0,0},
  {1,0,-32,0,160,0,-256,0,128,0,0,0},
  {0,9,0,-120,0,432,0,-576,0,256,0,0},
  {-1,0,50,0,-400,0,1120,0,-1280,0,512,0},
  {0,-11,0,220,0,-1232,0,2816,0,-2816,0,1024}
};

// grid = 576 x 256. Quarter-row (4 float4) per thread, 4 lanes/row.
// Measured 5.7us; LDG.128-issue bound (~3.6us floor).
__global__ void prep_rowsum_kernel(const float* __restrict__ w) {
    int t = blockIdx.x * 256 + threadIdx.x;   // 0..147455
    int r = t >> 2;                           // row 0..36863
    int q = t & 3;                            // quarter within row
    const float4* __restrict__ p = (const float4*)w + (size_t)r * 16 + q * 4;
    float4 v0 = __ldcs(p + 0);
    float4 v1 = __ldcs(p + 1);
    float4 v2 = __ldcs(p + 2);
    float4 v3 = __ldcs(p + 3);
    float s = ((v0.x + v0.y) + (v0.z + v0.w)) + ((v1.x + v1.y) + (v1.z + v1.w))
            + ((v2.x + v2.y) + (v2.z + v2.w)) + ((v3.x + v3.y) + (v3.z + v3.w));
    s += __shfl_xor_sync(0xffffffffu, s, 2);
    s += __shfl_xor_sync(0xffffffffu, s, 1);
    if (q == 0)
        g_wsum[r] = s * (1.0f / (64.0f * 4096.0f));
}

// 1024 threads: per (uv,c), fold symmetric pairs, expand x*Ti*Tj into Chebyshev
// basis (x*Ti*Tj = (T_{i+j+1}+T_{|i+j-1|}+T_{j-i+1}+T_{|j-i-1|})/4), then
// convert to monomial coefficients g[0..11].
#define ABSI(x) ((x) < 0 ? -(x) : (x))
#define ACCUM(i, j) { float wv = g_wsum[((uv * 36 + (i) * 6 + (j)) << 6) + c];   \
    if ((i) != (j)) wv += g_wsum[((uv * 36 + (j) * 6 + (i)) << 6) + c];          \
    wv *= 0.25f;                                                                  \
    h[(i)+(j)+1] += wv; h[ABSI((i)+(j)-1)] += wv;                                 \
    h[(j)-(i)+1] += wv; h[ABSI((j)-(i)-1)] += wv; }

__global__ void prep_transform_kernel() {
    int t = blockIdx.x * 256 + threadIdx.x;   // 0..1023 = (uv*64+c)
    if (t >= NS * NS * NC) return;
    int uv = t >> 6;
    int c = t & 63;
    float h[NG];
    #pragma unroll
    for (int r = 0; r < NG; r++) h[r] = 0.f;
    ACCUM(0,0) ACCUM(0,1) ACCUM(0,2) ACCUM(0,3) ACCUM(0,4) ACCUM(0,5)
    ACCUM(1,1) ACCUM(1,2) ACCUM(1,3) ACCUM(1,4) ACCUM(1,5)
    ACCUM(2,2) ACCUM(2,3) ACCUM(2,4) ACCUM(2,5)
    ACCUM(3,3) ACCUM(3,4) ACCUM(3,5)
    ACCUM(4,4) ACCUM(4,5)
    ACCUM(5,5)
    #pragma unroll
    for (int m = 0; m < NG; m++) {
        float g = 0.f;
        #pragma unroll
        for (int r = 0; r < NG; r++) g = fmaf(h[r], c_cheb[r][m], g);
        g_gcoef[(size_t)t * NG + m] = g;
    }
}

// ---- packed fp32x2 helpers (sm_100+) ----
typedef unsigned long long u64t;

__device__ __forceinline__ u64t pk2(float lo, float hi) {
    u64t r; asm("mov.b64 %0, {%1,%2};" : "=l"(r) : "f"(lo), "f"(hi)); return r;
}
__device__ __forceinline__ void upk2(u64t v, float& lo, float& hi) {
    asm("mov.b64 {%0,%1}, %2;" : "=f"(lo), "=f"(hi) : "l"(v));
}
__device__ __forceinline__ u64t fma2(u64t a, u64t b, u64t c) {
    u64t d; asm("fma.rn.f32x2 %0, %1, %2, %3;" : "=l"(d) : "l"(a), "l"(b), "l"(c)); return d;
}
__device__ __forceinline__ u64t add2(u64t a, u64t b) {
    u64t d; asm("add.rn.f32x2 %0, %1, %2;" : "=l"(d) : "l"(a), "l"(b)); return d;
}

// One CTA per (b,c,u,v) segment. 256 threads, 16 px/thread in regs.
// Streaming loads/stores; G coeffs prefetched to overlap min/max pass.
// Measured 24.5us (DRAM 43%).
__global__ __launch_bounds__(256, 4) void cft_main_kernel(const float* __restrict__ x,
                                                          float* __restrict__ out) {
    int seg = blockIdx.x;              // ((b*64+c)*4+u)*4+v
    int v = seg & 3;
    int u = (seg >> 2) & 3;
    int bc = seg >> 4;
    int c = bc & 63;
    size_t base = (size_t)bc * (HH * WW) + (size_t)u * HS * WW + (size_t)v * WS;
    const float4* __restrict__ xin = (const float4*)(x + base);
    int tid = threadIdx.x;
    int lane = tid & 31, warp = tid >> 5;

    float4 d[4];
    #pragma unroll
    for (int it = 0; it < 4; it++) {
        int q = it * 256 + tid;
        d[it] = __ldcs(xin + (q >> 4) * (WW / 4) + (q & 15));
    }

    // Issue the 12 coefficient loads NOW so their latency overlaps the min/max.
    const float* __restrict__ gp = g_gcoef + ((size_t)((u * NS + v) * NC) + c) * NG;
    float gs[NG];
    #pragma unroll
    for (int m = 0; m < NG; m++) gs[m] = __ldg(gp + m);

    // ---- pass 1: per-segment min/max ----
    float mn = d[0].x, mx = d[0].x;
    #pragma unroll
    for (int it = 0; it < 4; it++) {
        mn = fminf(mn, fminf(fminf(d[it].x, d[it].y), fminf(d[it].z, d[it].w)));
        mx = fmaxf(mx, fmaxf(fmaxf(d[it].x, d[it].y), fmaxf(d[it].z, d[it].w)));
    }
    #pragma unroll
    for (int off = 16; off; off >>= 1) {
        mn = fminf(mn, __shfl_xor_sync(0xffffffffu, mn, off));
        mx = fmaxf(mx, __shfl_xor_sync(0xffffffffu, mx, off));
    }
    __shared__ float s_mn[8], s_mx[8];
    __shared__ float s_part[8];
    if (lane == 0) { s_mn[warp] = mn; s_mx[warp] = mx; }
    __syncthreads();
    mn = s_mn[0]; mx = s_mx[0];
    #pragma unroll
    for (int k = 1; k < 8; k++) { mn = fminf(mn, s_mn[k]); mx = fmaxf(mx, s_mx[k]); }

    // ---- pass 2: packed Horner accumulation ----
    float a = 2.0f / (mx - mn + 1e-8f);
    float bb = fmaf(-mn, a, -1.0f);        // xn = x*a + bb
    u64t a2 = pk2(a, a);
    u64t b2 = pk2(bb, bb);
    u64t G[NG];
    #pragma unroll
    for (int m = 0; m < NG; m++) G[m] = pk2(gs[m], gs[m]);

    u64t acc = 0ull;   // {+0.0f,+0.0f}
    #pragma unroll
    for (int it = 0; it < 4; it++) {
        #pragma unroll
        for (int half = 0; half < 2; half++) {
            u64t val2 = half ? pk2(d[it].z, d[it].w) : pk2(d[it].x, d[it].y);
            u64t xn = fma2(val2, a2, b2);
            u64t p = G[11];
            #pragma unroll
            for (int m = 10; m >= 0; m--) p = fma2(p, xn, G[m]);
            acc = add2(acc, p);
        }
    }

    // ---- reduce one scalar across block; all threads finish redundantly ----
    float lo, hi; upk2(acc, lo, hi);
    float part = lo + hi;
    #pragma unroll
    for (int off = 16; off; off >>= 1)
        part += __shfl_xor_sync(0xffffffffu, part, off);
    if (lane == 0) s_part[warp] = part;
    __syncthreads();
    float s = s_part[0];
    #pragma unroll
    for (int k = 1; k < 8; k++) s += s_part[k];
    float sig = tanhf(s);

    // ---- broadcast-store the segment (streaming stores) ----
    float4 o4 = make_float4(sig, sig, sig, sig);
    float4* oo = (float4*)(out + base);
    #pragma unroll
    for (int it = 0; it < 4; it++) {
        int q = it * 256 + tid;
        __stcs(oo + (q >> 4) * (WW / 4) + (q & 15), o4);
    }
}

extern "C" void kernel_launch(void* const* d_in, const int* in_sizes, int n_in,
                              void* d_out, int out_size) {
    const float* x = (const float*)d_in[0];
    const float* w = (const float*)d_in[1];
    float* out = (float*)d_out;
    prep_rowsum_kernel<<<PREP_BLOCKS, 256>>>(w);
    prep_transform_kernel<<<4, 256>>>();
    cft_main_kernel<<<NB * NC * NS * NS, 256>>>(x, out);
}